// round 5
// baseline (speedup 1.0000x reference)
#include <cuda_runtime.h>
#include <cuda_bf16.h>
#include <math.h>
#include <cstdint>

// ---------------- static problem sizes ----------------
#define NB     32
#define SEQ    1024
#define NTOT   (NB*SEQ)     // 32768
#define DIM    128
#define NHEAD  4
#define HDIM   32
#define NLAY   3
#define DFF    2048
#define INDIM  64

// GEMM smem: 4 tiles (Ah,Al,Bh,Bl) x double buffer, each 128 rows x 36 floats
#define ROWF   36
#define TILEF  (128*ROWF)          // 4608 floats
#define BUFF   (4*TILEF)           // one stage: Ah,Al,Bh,Bl
#define SMEM_G (2*BUFF*4)          // bytes = 147456

// weight split buffer offsets (floats)
#define OFF_WIN   0
#define SZ_WIN    (DIM*INDIM)                      // 8192
#define LAYER_SZ  (3*DIM*DIM + DIM*DIM + DFF*DIM + DIM*DFF)  // 589824
#define OFF_QKV(l) (SZ_WIN + (l)*LAYER_SZ)
#define OFF_WO(l)  (OFF_QKV(l) + 3*DIM*DIM)
#define OFF_W1(l)  (OFF_WO(l) + DIM*DIM)
#define OFF_W2(l)  (OFF_W1(l) + DFF*DIM)
#define WTOT      (SZ_WIN + NLAY*LAYER_SZ)         // 1777664

// ---------------- scratch (device globals; no allocs allowed) ---------------
__device__ float g_h   [NTOT * DIM];
__device__ float g_qkv [NTOT * 3*DIM];
__device__ float g_attn[NTOT * DIM];
__device__ float g_tmp [NTOT * DIM];
__device__ float g_ffn [NTOT * DFF];
__device__ float g_mask[NTOT];
__device__ float g_Whi [WTOT];
__device__ float g_Wlo [WTOT];
__device__ float g_pool[NB * 8 * DIM];
__device__ float g_pm  [NB * 8];

__device__ __forceinline__ float* sel_buf(int id, const float* ext) {
    switch (id) {
        case 0: return g_h;
        case 1: return g_qkv;
        case 2: return g_attn;
        case 3: return g_tmp;
        case 4: return g_ffn;
        default: return (float*)ext;
    }
}

// ---------------- small PTX helpers ----------------
__device__ __forceinline__ uint32_t cvta_smem(const void* p) {
    uint32_t a;
    asm("{ .reg .u64 t; cvta.to.shared.u64 t, %1; cvt.u32.u64 %0, t; }"
        : "=r"(a) : "l"(p));
    return a;
}
__device__ __forceinline__ void cp16(uint32_t saddr, const void* gaddr) {
    asm volatile("cp.async.cg.shared.global [%0], [%1], 16;"
                 :: "r"(saddr), "l"(gaddr));
}
#define CP_COMMIT() asm volatile("cp.async.commit_group;" ::: "memory")
#define CP_WAIT0()  asm volatile("cp.async.wait_group 0;" ::: "memory")

__device__ __forceinline__ void tf32_split(float x, float& hi, float& lo) {
    uint32_t h;
    asm("cvt.rna.tf32.f32 %0, %1;" : "=r"(h) : "f"(x));
    hi = __uint_as_float(h);
    float r = x - hi;
    uint32_t l2;
    asm("cvt.rna.tf32.f32 %0, %1;" : "=r"(l2) : "f"(r));
    lo = __uint_as_float(l2);
}

__device__ __forceinline__ void mma8(float* d, float a0, float a1,
                                     float a2, float a3, float b0, float b1) {
    asm volatile(
        "mma.sync.aligned.m16n8k8.row.col.f32.tf32.tf32.f32 "
        "{%0,%1,%2,%3}, {%4,%5,%6,%7}, {%8,%9}, {%0,%1,%2,%3};"
        : "+f"(d[0]), "+f"(d[1]), "+f"(d[2]), "+f"(d[3])
        : "r"(__float_as_uint(a0)), "r"(__float_as_uint(a1)),
          "r"(__float_as_uint(a2)), "r"(__float_as_uint(a3)),
          "r"(__float_as_uint(b0)), "r"(__float_as_uint(b1)));
}

// ---------------- weight split + fragment-order permute ---------------------
// dst[woff + n*K + (k & ~31) + (k&3)*8 + ((k&31)>>2)] = split(src[n*K + k])
__global__ void __launch_bounds__(256) wsplit_k(
    const float* __restrict__ src, int woff, int count, int K)
{
    for (int idx = blockIdx.x * 256 + threadIdx.x; idx < count;
         idx += gridDim.x * 256) {
        const int k = idx % K;
        const float v = src[idx];
        float hi, lo;
        tf32_split(v, hi, lo);
        const int kin = k & 31;
        const int d = woff + (idx - k) + (k & ~31) + (kin & 3) * 8 + (kin >> 2);
        g_Whi[d] = hi;
        g_Wlo[d] = lo;
    }
}

// ---------------- 3xTF32 mma GEMM: C[M,Nc] = A[M,K] @ W[Nc,K]^T + bias -----
// 128x128 tile, 256 threads, warps 4(m)x2(n). K-chunks of 32. Weights come
// pre-split+permuted from g_Whi/g_Wlo via cp.async; activations LDG->split->STS.
// Smem fragment-order layout: elem (row,k) at row*36 + (k&3)*8 + (k>>2).
template<bool RELU>
__global__ void __launch_bounds__(256) gemm3_k(
    int aid, const float* __restrict__ aext,
    int woff, const float* __restrict__ bias,
    int cid, int Ncols, int K)
{
    extern __shared__ float sm[];
    const float* A = sel_buf(aid, aext);
    float*       C = sel_buf(cid, nullptr);

    const int bn = blockIdx.x * 128;
    const int bm = blockIdx.y * 128;

    const int tid  = threadIdx.x;
    const int lane = tid & 31;
    const int warp = tid >> 5;
    const int wm   = warp & 3;
    const int wn   = warp >> 2;
    const int g    = lane >> 2;
    const int cth  = lane & 3;

    // loader mapping: 2 threads per row
    const int lrow  = tid >> 1;
    const int khalf = tid & 1;

    const float* Abase = A + (size_t)(bm + lrow) * K + khalf * 16;
    const float* BhiB  = g_Whi + woff + (size_t)(bn + lrow) * K + khalf * 16;
    const float* BloB  = g_Wlo + woff + (size_t)(bn + lrow) * K + khalf * 16;

    // smem layout per stage: Ah, Al, Bh, Bl
    float* Ah[2] = { sm,             sm + BUFF };
    float* Al[2] = { sm + TILEF,     sm + BUFF + TILEF };
    float* Bh[2] = { sm + 2*TILEF,   sm + BUFF + 2*TILEF };
    float* Bl[2] = { sm + 3*TILEF,   sm + BUFF + 3*TILEF };
    const uint32_t sBh[2] = { cvta_smem(Bh[0]), cvta_smem(Bh[1]) };
    const uint32_t sBl[2] = { cvta_smem(Bl[0]), cvta_smem(Bl[1]) };
    const uint32_t bdst = (uint32_t)((lrow * ROWF + khalf * 16) * 4);

    float acc[2][8][4];
    #pragma unroll
    for (int mf = 0; mf < 2; mf++)
        #pragma unroll
        for (int nf = 0; nf < 8; nf++)
            #pragma unroll
            for (int j = 0; j < 4; j++) acc[mf][nf][j] = 0.f;

    const int nch = K >> 5;

    // prologue: B chunk0 via cp.async; A chunk0 into regs
    #pragma unroll
    for (int c4 = 0; c4 < 4; c4++) {
        cp16(sBh[0] + bdst + c4 * 16, BhiB + c4 * 4);
        cp16(sBl[0] + bdst + c4 * 16, BloB + c4 * 4);
    }
    CP_COMMIT();
    float4 pa[4];
    #pragma unroll
    for (int c4 = 0; c4 < 4; c4++)
        pa[c4] = *(const float4*)(Abase + c4 * 4);

    for (int ch = 0; ch < nch; ch++) {
        const int cur = ch & 1;
        const int nxt = cur ^ 1;

        // STS split A(ch): component w of pa[c4] -> off khalf*4 + c4 + w*8
        {
            float* ah = Ah[cur] + lrow * ROWF + khalf * 4;
            float* al = Al[cur] + lrow * ROWF + khalf * 4;
            #pragma unroll
            for (int c4 = 0; c4 < 4; c4++) {
                const float v[4] = { pa[c4].x, pa[c4].y, pa[c4].z, pa[c4].w };
                #pragma unroll
                for (int w = 0; w < 4; w++) {
                    float hi, lo;
                    tf32_split(v[w], hi, lo);
                    ah[c4 + w*8] = hi;
                    al[c4 + w*8] = lo;
                }
            }
        }
        // prefetch A(ch+1)
        if (ch + 1 < nch) {
            const int k0 = (ch + 1) << 5;
            #pragma unroll
            for (int c4 = 0; c4 < 4; c4++)
                pa[c4] = *(const float4*)(Abase + k0 + c4 * 4);
        }
        CP_WAIT0();            // B(ch) arrived
        __syncthreads();       // A(ch) stores visible; prev compute done
        if (ch + 1 < nch) {    // B(ch+1) overlaps compute(ch)
            const int k0 = (ch + 1) << 5;
            #pragma unroll
            for (int c4 = 0; c4 < 4; c4++) {
                cp16(sBh[nxt] + bdst + c4 * 16, BhiB + k0 + c4 * 4);
                cp16(sBl[nxt] + bdst + c4 * 16, BloB + k0 + c4 * 4);
            }
            CP_COMMIT();
        }

        // compute(ch)
        const float* ah = Ah[cur];
        const float* al = Al[cur];
        const float* bh = Bh[cur];
        const float* bl = Bl[cur];
        #pragma unroll
        for (int ksp = 0; ksp < 2; ksp++) {
            const int fo = cth * 8 + ksp * 4;   // in-row float offset
            float4 vh[2][2], vl[2][2];
            #pragma unroll
            for (int mf = 0; mf < 2; mf++) {
                const int r0 = wm * 32 + mf * 16 + g;
                vh[mf][0] = *(const float4*)(ah + r0 * ROWF + fo);
                vh[mf][1] = *(const float4*)(ah + (r0 + 8) * ROWF + fo);
                vl[mf][0] = *(const float4*)(al + r0 * ROWF + fo);
                vl[mf][1] = *(const float4*)(al + (r0 + 8) * ROWF + fo);
            }
            #pragma unroll
            for (int nf = 0; nf < 8; nf++) {
                const int n = wn * 64 + nf * 8 + g;
                const float4 wbh = *(const float4*)(bh + n * ROWF + fo);
                const float4 wbl = *(const float4*)(bl + n * ROWF + fo);
                #pragma unroll
                for (int mf = 0; mf < 2; mf++) {
                    float* d = acc[mf][nf];
                    // ks = 2*ksp  (components x,y)
                    mma8(d, vh[mf][0].x, vh[mf][1].x, vh[mf][0].y, vh[mf][1].y,
                            wbh.x, wbh.y);
                    mma8(d, vl[mf][0].x, vl[mf][1].x, vl[mf][0].y, vl[mf][1].y,
                            wbh.x, wbh.y);
                    mma8(d, vh[mf][0].x, vh[mf][1].x, vh[mf][0].y, vh[mf][1].y,
                            wbl.x, wbl.y);
                    // ks = 2*ksp+1 (components z,w)
                    mma8(d, vh[mf][0].z, vh[mf][1].z, vh[mf][0].w, vh[mf][1].w,
                            wbh.z, wbh.w);
                    mma8(d, vl[mf][0].z, vl[mf][1].z, vl[mf][0].w, vl[mf][1].w,
                            wbh.z, wbh.w);
                    mma8(d, vh[mf][0].z, vh[mf][1].z, vh[mf][0].w, vh[mf][1].w,
                            wbl.z, wbl.w);
                }
            }
        }
    }

    // epilogue
    #pragma unroll
    for (int nf = 0; nf < 8; nf++) {
        const int col = bn + wn*64 + nf*8 + cth*2;
        const float bx = __ldg(bias + col);
        const float by = __ldg(bias + col + 1);
        #pragma unroll
        for (int mf = 0; mf < 2; mf++) {
            const int row = bm + wm*32 + mf*16 + g;
            float2 v0 = make_float2(acc[mf][nf][0] + bx, acc[mf][nf][1] + by);
            float2 v1 = make_float2(acc[mf][nf][2] + bx, acc[mf][nf][3] + by);
            if (RELU) {
                v0.x = fmaxf(v0.x, 0.f); v0.y = fmaxf(v0.y, 0.f);
                v1.x = fmaxf(v1.x, 0.f); v1.y = fmaxf(v1.y, 0.f);
            }
            *(float2*)(C + (size_t)row * Ncols + col)       = v0;
            *(float2*)(C + (size_t)(row + 8) * Ncols + col) = v1;
        }
    }
}

// ---------------- flash attention: [key][d] tiles, cp.async double buffer ---
__global__ void __launch_bounds__(128) attn_k()
{
    __shared__ float Ks[2][64 * ROWF];
    __shared__ float Vs[2][64 * ROWF];

    const int blk = blockIdx.x;
    const int qt  = blk & 7;
    const int bh  = blk >> 3;
    const int b   = bh >> 2;
    const int h   = bh & 3;
    const int t   = threadIdx.x;
    const int qrow = qt * 128 + t;

    const float scale = 0.1767766952966369f;   // 1/sqrt(32)
    const float* base = g_qkv + (size_t)(b * SEQ) * (3*DIM) + h * HDIM;

    float q[HDIM];
    {
        const float4* qp = (const float4*)(base + (size_t)qrow * (3*DIM));
        #pragma unroll
        for (int i = 0; i < 8; i++) {
            float4 v = qp[i];
            q[4*i+0] = v.x * scale; q[4*i+1] = v.y * scale;
            q[4*i+2] = v.z * scale; q[4*i+3] = v.w * scale;
        }
    }

    float o[HDIM];
    #pragma unroll
    for (int d = 0; d < HDIM; d++) o[d] = 0.f;
    float m = -1e30f, l = 0.f;

    // loader: thread t -> row (t&63) of K (t<64) or V (t>=64)
    const int kr    = t & 63;
    const int which = t >> 6;
    const float* src0 = base + DIM * (1 + which) + (size_t)kr * (3*DIM);
    const uint32_t dK[2] = { cvta_smem(&Ks[0][kr*ROWF]), cvta_smem(&Ks[1][kr*ROWF]) };
    const uint32_t dV[2] = { cvta_smem(&Vs[0][kr*ROWF]), cvta_smem(&Vs[1][kr*ROWF]) };

    // prologue: tile 0
    {
        const uint32_t dst = which ? dV[0] : dK[0];
        #pragma unroll
        for (int c = 0; c < 8; c++) cp16(dst + c*16, src0 + c*4);
        CP_COMMIT();
    }

    for (int kt = 0; kt < SEQ/64; kt++) {
        const int cur = kt & 1;
        CP_WAIT0();
        __syncthreads();
        if (kt + 1 < SEQ/64) {
            const uint32_t dst = which ? dV[cur^1] : dK[cur^1];
            const float* srcn = src0 + (size_t)(kt + 1) * 64 * (3*DIM);
            #pragma unroll
            for (int c = 0; c < 8; c++) cp16(dst + c*16, srcn + c*4);
            CP_COMMIT();
        }

        const float* Kb = Ks[cur];
        const float* Vb = Vs[cur];
        #pragma unroll
        for (int qtr = 0; qtr < 4; qtr++) {
            float s[16];
            #pragma unroll
            for (int k = 0; k < 16; k++) {
                const float* kp = Kb + (qtr*16 + k) * ROWF;
                float a = 0.f;
                #pragma unroll
                for (int i = 0; i < 8; i++) {
                    const float4 kv = *(const float4*)(kp + i*4);
                    a = fmaf(q[4*i+0], kv.x, a);
                    a = fmaf(q[4*i+1], kv.y, a);
                    a = fmaf(q[4*i+2], kv.z, a);
                    a = fmaf(q[4*i+3], kv.w, a);
                }
                s[k] = a;
            }
            float tm = s[0];
            #pragma unroll
            for (int k = 1; k < 16; k++) tm = fmaxf(tm, s[k]);
            const float nm   = fmaxf(m, tm);
            const float corr = __expf(m - nm);
            l *= corr;
            #pragma unroll
            for (int d = 0; d < HDIM; d++) o[d] *= corr;
            #pragma unroll
            for (int k = 0; k < 16; k++) {
                const float p = __expf(s[k] - nm);
                l += p;
                const float* vp = Vb + (qtr*16 + k) * ROWF;
                #pragma unroll
                for (int i = 0; i < 8; i++) {
                    const float4 vv = *(const float4*)(vp + i*4);
                    o[4*i+0] = fmaf(p, vv.x, o[4*i+0]);
                    o[4*i+1] = fmaf(p, vv.y, o[4*i+1]);
                    o[4*i+2] = fmaf(p, vv.z, o[4*i+2]);
                    o[4*i+3] = fmaf(p, vv.w, o[4*i+3]);
                }
            }
            m = nm;
        }
        __syncthreads();
    }

    const float inv = 1.f / l;
    float* op = g_attn + (size_t)(b * SEQ + qrow) * DIM + h * HDIM;
    #pragma unroll
    for (int i = 0; i < 8; i++)
        ((float4*)op)[i] = make_float4(o[4*i+0]*inv, o[4*i+1]*inv,
                                       o[4*i+2]*inv, o[4*i+3]*inv);
}

// ---------------- residual add + LayerNorm (in place into g_h) --------------
__global__ void __launch_bounds__(256) add_ln_k(
    const float* __restrict__ gamma, const float* __restrict__ beta)
{
    const int warp = threadIdx.x >> 5;
    const int lane = threadIdx.x & 31;
    const int row  = blockIdx.x * 8 + warp;

    const float* r  = g_h   + (size_t)row * DIM;
    const float* dl = g_tmp + (size_t)row * DIM;

    float v[4];
    #pragma unroll
    for (int i = 0; i < 4; i++) v[i] = r[lane + 32*i] + dl[lane + 32*i];

    float s = v[0] + v[1] + v[2] + v[3];
    #pragma unroll
    for (int off = 16; off; off >>= 1) s += __shfl_xor_sync(~0u, s, off);
    const float mean = s * (1.f / DIM);

    float var = 0.f;
    #pragma unroll
    for (int i = 0; i < 4; i++) { float d = v[i] - mean; var = fmaf(d, d, var); }
    #pragma unroll
    for (int off = 16; off; off >>= 1) var += __shfl_xor_sync(~0u, var, off);
    const float inv = rsqrtf(var * (1.f / DIM) + 1e-5f);

    float* w = g_h + (size_t)row * DIM;
    #pragma unroll
    for (int i = 0; i < 4; i++) {
        const int c = lane + 32*i;
        w[c] = (v[i] - mean) * inv * gamma[c] + beta[c];
    }
}

// ---------------- node mask from post-projection h ---------------------------
__global__ void __launch_bounds__(256) mask_k()
{
    const int warp = threadIdx.x >> 5;
    const int lane = threadIdx.x & 31;
    const int row  = blockIdx.x * 8 + warp;
    const float* r = g_h + (size_t)row * DIM;
    float s = 0.f;
    #pragma unroll
    for (int i = 0; i < 4; i++) s += r[lane + 32*i];
    #pragma unroll
    for (int off = 16; off; off >>= 1) s += __shfl_xor_sync(~0u, s, off);
    if (lane == 0) g_mask[row] = (s != 0.f) ? 1.f : 0.f;
}

// ---------------- masked mean pooling (2 stage) -----------------------------
__global__ void __launch_bounds__(DIM) pool1_k()
{
    const int b  = blockIdx.y;
    const int c  = blockIdx.x;       // chunk of 128 rows
    const int d  = threadIdx.x;
    float acc = 0.f, ms = 0.f;
    const int r0 = b * SEQ + c * 128;
    for (int r = 0; r < 128; r++) {
        const float mk = g_mask[r0 + r];
        acc = fmaf(g_h[(size_t)(r0 + r) * DIM + d], mk, acc);
        ms += mk;
    }
    g_pool[(b * 8 + c) * DIM + d] = acc;
    if (d == 0) g_pm[b * 8 + c] = ms;
}

__global__ void __launch_bounds__(DIM) pool2_k(float* __restrict__ out)
{
    const int b = blockIdx.x;
    const int d = threadIdx.x;
    float acc = 0.f, ms = 0.f;
    #pragma unroll
    for (int c = 0; c < 8; c++) {
        acc += g_pool[(b * 8 + c) * DIM + d];
        ms  += g_pm[b * 8 + c];
    }
    out[b * DIM + d] = acc / ms;
}

// ---------------- driver -----------------------------------------------------
extern "C" void kernel_launch(void* const* d_in, const int* in_sizes, int n_in,
                              void* d_out, int out_size)
{
    const float* x     = (const float*)d_in[0];   // [N, 64]
    const float* W_in  = (const float*)d_in[2];   // [128, 64]
    const float* b_in  = (const float*)d_in[3];   // [128]
    const float* Wqkv  = (const float*)d_in[4];   // [L, 384, 128]
    const float* bqkv  = (const float*)d_in[5];   // [L, 384]
    const float* Wo    = (const float*)d_in[6];   // [L, 128, 128]
    const float* bo    = (const float*)d_in[7];   // [L, 128]
    const float* W1    = (const float*)d_in[8];   // [L, 2048, 128]
    const float* b1    = (const float*)d_in[9];   // [L, 2048]
    const float* W2    = (const float*)d_in[10];  // [L, 128, 2048]
    const float* b2    = (const float*)d_in[11];  // [L, 128]
    const float* ln1g  = (const float*)d_in[12];
    const float* ln1b  = (const float*)d_in[13];
    const float* ln2g  = (const float*)d_in[14];
    const float* ln2b  = (const float*)d_in[15];
    float* out = (float*)d_out;

    static bool attr_done = false;
    if (!attr_done) {
        cudaFuncSetAttribute(gemm3_k<false>,
            cudaFuncAttributeMaxDynamicSharedMemorySize, SMEM_G);
        cudaFuncSetAttribute(gemm3_k<true>,
            cudaFuncAttributeMaxDynamicSharedMemorySize, SMEM_G);
        attr_done = true;
    }

    // ---- weight split/permute (cheap, once per call) ----
    wsplit_k<<<32, 256>>>(W_in, OFF_WIN, SZ_WIN, INDIM);
    for (int l = 0; l < NLAY; l++) {
        wsplit_k<<<192, 256>>>(Wqkv + (size_t)l*3*DIM*DIM, OFF_QKV(l), 3*DIM*DIM, DIM);
        wsplit_k<<<64,  256>>>(Wo   + (size_t)l*DIM*DIM,   OFF_WO(l),  DIM*DIM,   DIM);
        wsplit_k<<<512, 256>>>(W1   + (size_t)l*DFF*DIM,   OFF_W1(l),  DFF*DIM,   DIM);
        wsplit_k<<<512, 256>>>(W2   + (size_t)l*DIM*DFF,   OFF_W2(l),  DIM*DFF,   DFF);
    }

    const int MROW = NTOT / 128;   // 256 row-tiles

    gemm3_k<false><<<dim3(1, MROW), 256, SMEM_G>>>(5, x, OFF_WIN, b_in, 0, DIM, INDIM);
    mask_k<<<NTOT/8, 256>>>();

    for (int l = 0; l < NLAY; l++) {
        gemm3_k<false><<<dim3(3, MROW), 256, SMEM_G>>>(
            0, nullptr, OFF_QKV(l), bqkv + l*3*DIM, 1, 3*DIM, DIM);
        attn_k<<<NB*NHEAD*(SEQ/128), 128>>>();
        gemm3_k<false><<<dim3(1, MROW), 256, SMEM_G>>>(
            2, nullptr, OFF_WO(l), bo + l*DIM, 3, DIM, DIM);
        add_ln_k<<<NTOT/8, 256>>>(ln1g + l*DIM, ln1b + l*DIM);
        gemm3_k<true><<<dim3(DFF/128, MROW), 256, SMEM_G>>>(
            0, nullptr, OFF_W1(l), b1 + l*DFF, 4, DFF, DIM);
        gemm3_k<false><<<dim3(1, MROW), 256, SMEM_G>>>(
            4, nullptr, OFF_W2(l), b2 + l*DIM, 3, DIM, DFF);
        add_ln_k<<<NTOT/8, 256>>>(ln2g + l*DIM, ln2b + l*DIM);
    }

    pool1_k<<<dim3(8, NB), DIM>>>();
    pool2_k<<<NB, DIM>>>(out);
}

// round 8
// speedup vs baseline: 1.5935x; 1.5935x over previous
#include <cuda_runtime.h>
#include <cuda_bf16.h>
#include <math.h>
#include <cstdint>

// ---------------- static problem sizes ----------------
#define NB     32
#define SEQ    1024
#define NTOT   (NB*SEQ)     // 32768
#define DIM    128
#define NHEAD  4
#define HDIM   32
#define NLAY   3
#define DFF    2048
#define INDIM  64

#define SMPAD  36           // floats per smem row (conflict-free frag gathers)
#define TILEB  (128*SMPAD)  // floats per tile buffer
#define SMEM_DYN (4*TILEB*4) // bytes: A0,B0,A1,B1 = 73728 -> 2 CTA/SM

// ---------------- scratch (device globals; no allocs allowed) ---------------
__device__ float g_h   [NTOT * DIM];
__device__ float g_qkv [NTOT * 3*DIM];
__device__ float g_attn[NTOT * DIM];
__device__ float g_tmp [NTOT * DIM];
__device__ float g_ffn [NTOT * DFF];
__device__ float g_mask[NTOT];
__device__ float g_pool[NB * 8 * DIM];
__device__ float g_pm  [NB * 8];

__device__ __forceinline__ float* sel_buf(int id, const float* ext) {
    switch (id) {
        case 0: return g_h;
        case 1: return g_qkv;
        case 2: return g_attn;
        case 3: return g_tmp;
        case 4: return g_ffn;
        default: return (float*)ext;
    }
}

// ---------------- small PTX helpers ----------------
__device__ __forceinline__ uint32_t cvta_smem(const void* p) {
    uint32_t a;
    asm("{ .reg .u64 t; cvta.to.shared.u64 t, %1; cvt.u32.u64 %0, t; }"
        : "=r"(a) : "l"(p));
    return a;
}
__device__ __forceinline__ void cp16(uint32_t saddr, const void* gaddr) {
    asm volatile("cp.async.cg.shared.global [%0], [%1], 16;"
                 :: "r"(saddr), "l"(gaddr));
}
#define CP_COMMIT() asm volatile("cp.async.commit_group;" ::: "memory")
#define CP_WAIT0()  asm volatile("cp.async.wait_group 0;" ::: "memory")
#define CP_WAIT1()  asm volatile("cp.async.wait_group 1;" ::: "memory")

__device__ __forceinline__ void tf32_split(float x, uint32_t& hi, uint32_t& lo) {
    asm("cvt.rna.tf32.f32 %0, %1;" : "=r"(hi) : "f"(x));
    float r = x - __uint_as_float(hi);
    asm("cvt.rna.tf32.f32 %0, %1;" : "=r"(lo) : "f"(r));
}
__device__ __forceinline__ void tf32_split_f(float x, float& hi, float& lo) {
    uint32_t h, l2;
    tf32_split(x, h, l2);
    hi = __uint_as_float(h);
    lo = __uint_as_float(l2);
}
__device__ __forceinline__ float cvt_tf32(float x) {
    uint32_t u;
    asm("cvt.rna.tf32.f32 %0, %1;" : "=r"(u) : "f"(x));
    return __uint_as_float(u);
}

__device__ __forceinline__ void mma8(float* d, float a0, float a1,
                                     float a2, float a3, float b0, float b1) {
    asm volatile(
        "mma.sync.aligned.m16n8k8.row.col.f32.tf32.tf32.f32 "
        "{%0,%1,%2,%3}, {%4,%5,%6,%7}, {%8,%9}, {%0,%1,%2,%3};"
        : "+f"(d[0]), "+f"(d[1]), "+f"(d[2]), "+f"(d[3])
        : "r"(__float_as_uint(a0)), "r"(__float_as_uint(a1)),
          "r"(__float_as_uint(a2)), "r"(__float_as_uint(a3)),
          "r"(__float_as_uint(b0)), "r"(__float_as_uint(b1)));
}

// ---------------- 3xTF32 mma GEMM (72KB smem, 2 CTA/SM) ---------------------
template<bool RELU>
__global__ void __launch_bounds__(256) gemm_mma_k(
    int aid, const float* __restrict__ aext,
    const float* __restrict__ W, const float* __restrict__ bias,
    int cid, int Ncols, int K)
{
    extern __shared__ float sm[];
    float* bufA[2] = { sm,            sm + 2*TILEB };
    float* bufB[2] = { sm + TILEB,    sm + 3*TILEB };

    const float* A = sel_buf(aid, aext);
    float*       C = sel_buf(cid, nullptr);

    const int bm = blockIdx.y * 128;
    const int bn = blockIdx.x * 128;

    const int tid  = threadIdx.x;
    const int lane = tid & 31;
    const int warp = tid >> 5;
    const int wm   = warp & 3;
    const int wn   = warp >> 2;
    const int g    = lane >> 2;
    const int cth  = lane & 3;

    const int lrow = tid >> 3;
    const int lc4  = tid & 7;
    const float* Abase = A + (size_t)(bm + lrow) * K + lc4 * 4;
    const float* Wbase = W + (size_t)(bn + lrow) * K + lc4 * 4;
    const uint32_t sA[2] = { cvta_smem(bufA[0]), cvta_smem(bufA[1]) };
    const uint32_t sB[2] = { cvta_smem(bufB[0]), cvta_smem(bufB[1]) };
    const uint32_t soff  = (uint32_t)((lrow * SMPAD + lc4 * 4) * 4);

    float acc[2][8][4];
    #pragma unroll
    for (int mf = 0; mf < 2; mf++)
        #pragma unroll
        for (int nf = 0; nf < 8; nf++)
            #pragma unroll
            for (int j = 0; j < 4; j++) acc[mf][nf][j] = 0.f;

    const int nch = K >> 5;

    #pragma unroll
    for (int i = 0; i < 4; i++) {
        const uint32_t so = soff + (uint32_t)(i * 32 * SMPAD * 4);
        cp16(sA[0] + so, Abase + (size_t)i * 32 * K);
        cp16(sB[0] + so, Wbase + (size_t)i * 32 * K);
    }
    CP_COMMIT();

    for (int ch = 0; ch < nch; ch++) {
        const int cur = ch & 1;
        if (ch + 1 < nch) {
            const int nxt = cur ^ 1;
            const int k0 = (ch + 1) << 5;
            #pragma unroll
            for (int i = 0; i < 4; i++) {
                const uint32_t so = soff + (uint32_t)(i * 32 * SMPAD * 4);
                cp16(sA[nxt] + so, Abase + (size_t)i * 32 * K + k0);
                cp16(sB[nxt] + so, Wbase + (size_t)i * 32 * K + k0);
            }
            CP_COMMIT();
            CP_WAIT1();
        } else {
            CP_WAIT0();
        }
        __syncthreads();

        const float* As = bufA[cur];
        const float* Bs = bufB[cur];

        #pragma unroll
        for (int ks = 0; ks < 4; ks++) {
            const int kb = ks * 8 + cth;

            float ah[2][4], al[2][4];
            #pragma unroll
            for (int mf = 0; mf < 2; mf++) {
                const float* ar = As + (wm*32 + mf*16 + g) * SMPAD;
                tf32_split_f(ar[kb],             ah[mf][0], al[mf][0]);
                tf32_split_f(ar[8*SMPAD + kb],   ah[mf][1], al[mf][1]);
                tf32_split_f(ar[kb + 4],         ah[mf][2], al[mf][2]);
                tf32_split_f(ar[8*SMPAD + kb+4], ah[mf][3], al[mf][3]);
            }
            #pragma unroll
            for (int nf = 0; nf < 8; nf++) {
                const float* br = Bs + (wn*64 + nf*8 + g) * SMPAD;
                float bh0, bl0, bh1, bl1;
                tf32_split_f(br[kb],     bh0, bl0);
                tf32_split_f(br[kb + 4], bh1, bl1);
                #pragma unroll
                for (int mf = 0; mf < 2; mf++) {
                    float* d = acc[mf][nf];
                    mma8(d, ah[mf][0], ah[mf][1], ah[mf][2], ah[mf][3], bh0, bh1);
                    mma8(d, al[mf][0], al[mf][1], al[mf][2], al[mf][3], bh0, bh1);
                    mma8(d, ah[mf][0], ah[mf][1], ah[mf][2], ah[mf][3], bl0, bl1);
                }
            }
        }
        __syncthreads();
    }

    #pragma unroll
    for (int nf = 0; nf < 8; nf++) {
        const int col = bn + wn*64 + nf*8 + cth*2;
        const float bx = __ldg(bias + col);
        const float by = __ldg(bias + col + 1);
        #pragma unroll
        for (int mf = 0; mf < 2; mf++) {
            const int row = bm + wm*32 + mf*16 + g;
            float2 v0 = make_float2(acc[mf][nf][0] + bx, acc[mf][nf][1] + by);
            float2 v1 = make_float2(acc[mf][nf][2] + bx, acc[mf][nf][3] + by);
            if (RELU) {
                v0.x = fmaxf(v0.x, 0.f); v0.y = fmaxf(v0.y, 0.f);
                v1.x = fmaxf(v1.x, 0.f); v1.y = fmaxf(v1.y, 0.f);
            }
            *(float2*)(C + (size_t)row * Ncols + col)       = v0;
            *(float2*)(C + (size_t)(row + 8) * Ncols + col) = v1;
        }
    }
}

// ---------------- MMA flash attention ---------------------------------------
// 128 threads (4 warps); CTA = 128 q-rows of one (b,h); warp = 32 rows.
// Key tiles of 32. QK^T: 3xTF32 (Q split in regs, K split in smem).
// PV: single tf32 (P cvt.rna, V pre-cvt by loader, stored transposed).
__global__ void __launch_bounds__(128) attn_k()
{
    __shared__ float Khi[32*SMPAD];
    __shared__ float Klo[32*SMPAD];
    __shared__ float Vt [32*SMPAD];          // [dim][key]
    __shared__ float Ps [4][32*SMPAD];       // per-warp P staging

    const int blk = blockIdx.x;
    const int qt  = blk & 7;
    const int bh  = blk >> 3;
    const int b   = bh >> 2;
    const int h   = bh & 3;
    const int tid  = threadIdx.x;
    const int lane = tid & 31;
    const int w    = tid >> 5;
    const int g    = lane >> 2;
    const int cth  = lane & 3;

    const float scale = 0.1767766952966369f;   // 1/sqrt(32)
    const float* base = g_qkv + (size_t)(b * SEQ) * (3*DIM) + h * HDIM;
    const int qbase = qt * 128 + w * 32;

    // ---- Q fragments (scaled, split hi/lo) ----
    float qh[2][4][4], ql[2][4][4];
    #pragma unroll
    for (int mt = 0; mt < 2; mt++) {
        #pragma unroll
        for (int kc = 0; kc < 4; kc++) {
            const float* q0 = base + (size_t)(qbase + mt*16 + g) * (3*DIM) + kc*8 + cth;
            const float* q1 = q0 + (size_t)8 * (3*DIM);
            tf32_split_f(q0[0] * scale, qh[mt][kc][0], ql[mt][kc][0]);
            tf32_split_f(q1[0] * scale, qh[mt][kc][1], ql[mt][kc][1]);
            tf32_split_f(q0[4] * scale, qh[mt][kc][2], ql[mt][kc][2]);
            tf32_split_f(q1[4] * scale, qh[mt][kc][3], ql[mt][kc][3]);
        }
    }

    float o[2][4][4];
    #pragma unroll
    for (int mt = 0; mt < 2; mt++)
        #pragma unroll
        for (int nt = 0; nt < 4; nt++)
            #pragma unroll
            for (int j = 0; j < 4; j++) o[mt][nt][j] = 0.f;
    float m_[2][2] = { {-1e30f, -1e30f}, {-1e30f, -1e30f} };
    float l_[2][2] = { {0.f, 0.f}, {0.f, 0.f} };

    // loader: thread -> key (tid>>2), dim segment (tid&3)*8
    const int key  = tid >> 2;
    const int dseg = (tid & 3) * 8;
    const float* kp0 = base + DIM   + (size_t)key * (3*DIM) + dseg;
    const float* vp0 = base + 2*DIM + (size_t)key * (3*DIM) + dseg;

    // prefetch tile 0
    float4 rk0 = *(const float4*)(kp0);
    float4 rk1 = *(const float4*)(kp0 + 4);
    float4 rv0 = *(const float4*)(vp0);
    float4 rv1 = *(const float4*)(vp0 + 4);

    float* pw = Ps[w];

    for (int t = 0; t < 32; t++) {
        __syncthreads();   // all warps done with previous tile's K/V smem
        // split K -> Khi/Klo [key][dim]; V -> Vt [dim][key] (tf32-rounded)
        {
            float* khr = Khi + key * SMPAD + dseg;
            float* klr = Klo + key * SMPAD + dseg;
            const float kv[8] = { rk0.x, rk0.y, rk0.z, rk0.w,
                                  rk1.x, rk1.y, rk1.z, rk1.w };
            const float vv[8] = { rv0.x, rv0.y, rv0.z, rv0.w,
                                  rv1.x, rv1.y, rv1.z, rv1.w };
            #pragma unroll
            for (int j = 0; j < 8; j++) {
                float hi, lo;
                tf32_split_f(kv[j], hi, lo);
                khr[j] = hi;
                klr[j] = lo;
                Vt[(dseg + j) * SMPAD + key] = cvt_tf32(vv[j]);
            }
        }
        __syncthreads();   // tile t visible
        // prefetch tile t+1 (overlaps compute below)
        if (t + 1 < 32) {
            const size_t off = (size_t)(t + 1) * 32 * (3*DIM);
            rk0 = *(const float4*)(kp0 + off);
            rk1 = *(const float4*)(kp0 + off + 4);
            rv0 = *(const float4*)(vp0 + off);
            rv1 = *(const float4*)(vp0 + off + 4);
        }

        // ---- S = Q @ K^T (3xTF32) ----
        float s[2][4][4];
        #pragma unroll
        for (int mt = 0; mt < 2; mt++)
            #pragma unroll
            for (int nt = 0; nt < 4; nt++)
                #pragma unroll
                for (int j = 0; j < 4; j++) s[mt][nt][j] = 0.f;

        #pragma unroll
        for (int nt = 0; nt < 4; nt++) {
            #pragma unroll
            for (int kc = 0; kc < 4; kc++) {
                const int off = (nt*8 + g) * SMPAD + kc*8 + cth;
                const float bh0 = Khi[off], bh1 = Khi[off + 4];
                const float bl0 = Klo[off], bl1 = Klo[off + 4];
                #pragma unroll
                for (int mt = 0; mt < 2; mt++) {
                    float* d = s[mt][nt];
                    const float* AH = qh[mt][kc];
                    const float* AL = ql[mt][kc];
                    mma8(d, AH[0], AH[1], AH[2], AH[3], bh0, bh1);
                    mma8(d, AL[0], AL[1], AL[2], AL[3], bh0, bh1);
                    mma8(d, AH[0], AH[1], AH[2], AH[3], bl0, bl1);
                }
            }
        }

        // ---- softmax update (per row-slot; quad shuffles) ----
        #pragma unroll
        for (int mt = 0; mt < 2; mt++) {
            #pragma unroll
            for (int r = 0; r < 2; r++) {
                float rm = -1e30f;
                #pragma unroll
                for (int nt = 0; nt < 4; nt++)
                    rm = fmaxf(rm, fmaxf(s[mt][nt][2*r], s[mt][nt][2*r+1]));
                rm = fmaxf(rm, __shfl_xor_sync(0xffffffffu, rm, 1));
                rm = fmaxf(rm, __shfl_xor_sync(0xffffffffu, rm, 2));
                const float nm   = fmaxf(m_[mt][r], rm);
                const float corr = __expf(m_[mt][r] - nm);
                float ts = 0.f;
                #pragma unroll
                for (int nt = 0; nt < 4; nt++) {
                    const float p0 = __expf(s[mt][nt][2*r]   - nm);
                    const float p1 = __expf(s[mt][nt][2*r+1] - nm);
                    s[mt][nt][2*r]   = p0;
                    s[mt][nt][2*r+1] = p1;
                    ts += p0 + p1;
                    o[mt][nt][2*r]   *= corr;
                    o[mt][nt][2*r+1] *= corr;
                }
                ts += __shfl_xor_sync(0xffffffffu, ts, 1);
                ts += __shfl_xor_sync(0xffffffffu, ts, 2);
                l_[mt][r] = l_[mt][r] * corr + ts;
                m_[mt][r] = nm;
            }
        }

        // ---- P -> per-warp smem (tf32-rounded) ----
        #pragma unroll
        for (int mt = 0; mt < 2; mt++)
            #pragma unroll
            for (int r = 0; r < 2; r++)
                #pragma unroll
                for (int nt = 0; nt < 4; nt++) {
                    const int row = mt*16 + r*8 + g;
                    float2 pv = make_float2(cvt_tf32(s[mt][nt][2*r]),
                                            cvt_tf32(s[mt][nt][2*r+1]));
                    *(float2*)(pw + row * SMPAD + nt*8 + 2*cth) = pv;
                }
        __syncwarp();

        // ---- O += P @ V (single tf32) ----
        #pragma unroll
        for (int kc = 0; kc < 4; kc++) {
            float a[2][4];
            #pragma unroll
            for (int mt = 0; mt < 2; mt++) {
                const float* pr = pw + (mt*16 + g) * SMPAD + kc*8 + cth;
                a[mt][0] = pr[0];
                a[mt][1] = pr[8*SMPAD];
                a[mt][2] = pr[4];
                a[mt][3] = pr[8*SMPAD + 4];
            }
            #pragma unroll
            for (int nt = 0; nt < 4; nt++) {
                const int vo = (nt*8 + g) * SMPAD + kc*8 + cth;
                const float b0 = Vt[vo], b1 = Vt[vo + 4];
                #pragma unroll
                for (int mt = 0; mt < 2; mt++)
                    mma8(o[mt][nt], a[mt][0], a[mt][1], a[mt][2], a[mt][3], b0, b1);
            }
        }
        __syncwarp();   // P region safe to overwrite next tile
    }

    // ---- normalize and store (FIX: global row includes b*SEQ) ----
    #pragma unroll
    for (int mt = 0; mt < 2; mt++) {
        #pragma unroll
        for (int r = 0; r < 2; r++) {
            const float inv = 1.f / l_[mt][r];
            const int row = qbase + mt*16 + r*8 + g;
            float* orow = g_attn + (size_t)(b * SEQ + row) * DIM + h * HDIM;
            #pragma unroll
            for (int nt = 0; nt < 4; nt++) {
                float2 v = make_float2(o[mt][nt][2*r] * inv,
                                       o[mt][nt][2*r+1] * inv);
                *(float2*)(orow + nt*8 + 2*cth) = v;
            }
        }
    }
}

// ---------------- residual add + LayerNorm (in place into g_h) --------------
__global__ void __launch_bounds__(256) add_ln_k(
    const float* __restrict__ gamma, const float* __restrict__ beta)
{
    const int warp = threadIdx.x >> 5;
    const int lane = threadIdx.x & 31;
    const int row  = blockIdx.x * 8 + warp;

    const float* r  = g_h   + (size_t)row * DIM;
    const float* dl = g_tmp + (size_t)row * DIM;

    float v[4];
    #pragma unroll
    for (int i = 0; i < 4; i++) v[i] = r[lane + 32*i] + dl[lane + 32*i];

    float s = v[0] + v[1] + v[2] + v[3];
    #pragma unroll
    for (int off = 16; off; off >>= 1) s += __shfl_xor_sync(~0u, s, off);
    const float mean = s * (1.f / DIM);

    float var = 0.f;
    #pragma unroll
    for (int i = 0; i < 4; i++) { float d = v[i] - mean; var = fmaf(d, d, var); }
    #pragma unroll
    for (int off = 16; off; off >>= 1) var += __shfl_xor_sync(~0u, var, off);
    const float inv = rsqrtf(var * (1.f / DIM) + 1e-5f);

    float* w = g_h + (size_t)row * DIM;
    #pragma unroll
    for (int i = 0; i < 4; i++) {
        const int c = lane + 32*i;
        w[c] = (v[i] - mean) * inv * gamma[c] + beta[c];
    }
}

// ---------------- node mask from post-projection h ---------------------------
__global__ void __launch_bounds__(256) mask_k()
{
    const int warp = threadIdx.x >> 5;
    const int lane = threadIdx.x & 31;
    const int row  = blockIdx.x * 8 + warp;
    const float* r = g_h + (size_t)row * DIM;
    float s = 0.f;
    #pragma unroll
    for (int i = 0; i < 4; i++) s += r[lane + 32*i];
    #pragma unroll
    for (int off = 16; off; off >>= 1) s += __shfl_xor_sync(~0u, s, off);
    if (lane == 0) g_mask[row] = (s != 0.f) ? 1.f : 0.f;
}

// ---------------- masked mean pooling (2 stage) -----------------------------
__global__ void __launch_bounds__(DIM) pool1_k()
{
    const int b  = blockIdx.y;
    const int c  = blockIdx.x;
    const int d  = threadIdx.x;
    float acc = 0.f, ms = 0.f;
    const int r0 = b * SEQ + c * 128;
    for (int r = 0; r < 128; r++) {
        const float mk = g_mask[r0 + r];
        acc = fmaf(g_h[(size_t)(r0 + r) * DIM + d], mk, acc);
        ms += mk;
    }
    g_pool[(b * 8 + c) * DIM + d] = acc;
    if (d == 0) g_pm[b * 8 + c] = ms;
}

__global__ void __launch_bounds__(DIM) pool2_k(float* __restrict__ out)
{
    const int b = blockIdx.x;
    const int d = threadIdx.x;
    float acc = 0.f, ms = 0.f;
    #pragma unroll
    for (int c = 0; c < 8; c++) {
        acc += g_pool[(b * 8 + c) * DIM + d];
        ms  += g_pm[b * 8 + c];
    }
    out[b * DIM + d] = acc / ms;
}

// ---------------- driver -----------------------------------------------------
extern "C" void kernel_launch(void* const* d_in, const int* in_sizes, int n_in,
                              void* d_out, int out_size)
{
    const float* x     = (const float*)d_in[0];   // [N, 64]
    const float* W_in  = (const float*)d_in[2];   // [128, 64]
    const float* b_in  = (const float*)d_in[3];   // [128]
    const float* Wqkv  = (const float*)d_in[4];   // [L, 384, 128]
    const float* bqkv  = (const float*)d_in[5];   // [L, 384]
    const float* Wo    = (const float*)d_in[6];   // [L, 128, 128]
    const float* bo    = (const float*)d_in[7];   // [L, 128]
    const float* W1    = (const float*)d_in[8];   // [L, 2048, 128]
    const float* b1    = (const float*)d_in[9];   // [L, 2048]
    const float* W2    = (const float*)d_in[10];  // [L, 128, 2048]
    const float* b2    = (const float*)d_in[11];  // [L, 128]
    const float* ln1g  = (const float*)d_in[12];
    const float* ln1b  = (const float*)d_in[13];
    const float* ln2g  = (const float*)d_in[14];
    const float* ln2b  = (const float*)d_in[15];
    float* out = (float*)d_out;

    static bool attr_done = false;
    if (!attr_done) {
        cudaFuncSetAttribute(gemm_mma_k<false>,
            cudaFuncAttributeMaxDynamicSharedMemorySize, SMEM_DYN);
        cudaFuncSetAttribute(gemm_mma_k<true>,
            cudaFuncAttributeMaxDynamicSharedMemorySize, SMEM_DYN);
        attr_done = true;
    }

    const int MROW = NTOT / 128;   // 256 row-tiles

    gemm_mma_k<false><<<dim3(1, MROW), 256, SMEM_DYN>>>(5, x, W_in, b_in, 0, DIM, INDIM);
    mask_k<<<NTOT/8, 256>>>();

    for (int l = 0; l < NLAY; l++) {
        gemm_mma_k<false><<<dim3(3, MROW), 256, SMEM_DYN>>>(
            0, nullptr, Wqkv + (size_t)l*3*DIM*DIM, bqkv + l*3*DIM, 1, 3*DIM, DIM);
        attn_k<<<NB*NHEAD*(SEQ/128), 128>>>();
        gemm_mma_k<false><<<dim3(1, MROW), 256, SMEM_DYN>>>(
            2, nullptr, Wo + (size_t)l*DIM*DIM, bo + l*DIM, 3, DIM, DIM);
        add_ln_k<<<NTOT/8, 256>>>(ln1g + l*DIM, ln1b + l*DIM);
        gemm_mma_k<true><<<dim3(DFF/128, MROW), 256, SMEM_DYN>>>(
            0, nullptr, W1 + (size_t)l*DFF*DIM, b1 + l*DFF, 4, DFF, DIM);
        gemm_mma_k<false><<<dim3(1, MROW), 256, SMEM_DYN>>>(
            4, nullptr, W2 + (size_t)l*DIM*DFF, b2 + l*DIM, 3, DIM, DFF);
        add_ln_k<<<NTOT/8, 256>>>(ln2g + l*DIM, ln2b + l*DIM);
    }

    pool1_k<<<dim3(8, NB), DIM>>>();
    pool2_k<<<NB, DIM>>>(out);
}